// round 6
// baseline (speedup 1.0000x reference)
#include <cuda_runtime.h>
#include <math_constants.h>

#define N_SPAT 8000
#define CIN 64
#define DQK 8
#define DV 64
#define LOG2E_F 1.4426950408889634f
#define JSPLIT 4

typedef unsigned long long ull;

// ---------------- scratch (no allocations allowed) ----------------
__device__ float g_Q[2 * N_SPAT * DQK];             // [b][i][c8]
__device__ float g_K[2 * N_SPAT * DQK];             // [b][j][c8]
__device__ float g_V[2 * N_SPAT * DV];              // [b][j][c64]
__device__ float g_Opart[JSPLIT * 2 * N_SPAT * DV]; // [s][b][i][c]
__device__ float g_m[JSPLIT * 2 * N_SPAT];
__device__ float g_l[JSPLIT * 2 * N_SPAT];

// ---------------- f32x2 helpers (FFMA2 path, sm_10x) ----------------
__device__ __forceinline__ ull dup2(float x) {
    ull r;
    asm("mov.b64 %0, {%1, %1};" : "=l"(r) : "r"(__float_as_uint(x)));
    return r;
}
__device__ __forceinline__ ull pack2(float lo, float hi) {
    ull r;
    asm("mov.b64 %0, {%1, %2};" : "=l"(r) : "r"(__float_as_uint(lo)), "r"(__float_as_uint(hi)));
    return r;
}
__device__ __forceinline__ void fma2(ull& d, ull a, ull b) {
    asm("fma.rn.f32x2 %0, %1, %2, %0;" : "+l"(d) : "l"(a), "l"(b));
}
__device__ __forceinline__ ull mul2(ull a, ull b) {
    ull r;
    asm("mul.rn.f32x2 %0, %1, %2;" : "=l"(r) : "l"(a), "l"(b));
    return r;
}
__device__ __forceinline__ float lo32(ull v) { return __uint_as_float((unsigned)v); }
__device__ __forceinline__ float hi32(ull v) { return __uint_as_float((unsigned)(v >> 32)); }

// ---------------- cp.async helpers ----------------
__device__ __forceinline__ void cp_async16(void* smem, const void* gmem) {
    unsigned saddr = (unsigned)__cvta_generic_to_shared(smem);
    asm volatile("cp.async.cg.shared.global [%0], [%1], 16;\n" :: "r"(saddr), "l"(gmem));
}
__device__ __forceinline__ void cp_commit() { asm volatile("cp.async.commit_group;\n"); }
__device__ __forceinline__ void cp_wait0() { asm volatile("cp.async.wait_group 0;\n"); }

// =====================================================================
// Conv kernel: fused Q/K/V 3x3x3 SAME conv, 4 voxels per thread.
// Grid (5 ocGroups, 20 z, 2 b) = 200 CTAs, block 128.
// Slab stored as DUPLICATED f32 pairs (LDS.64 broadcast operand, no MOV).
// Per tap: 8 weight LDS.64 (regs) + 4 slab LDS.64 + 32 FFMA2.
// Dynamic smem: slab2 4*3*484*8 = 46464 B + weights 6912 B = 53376 B.
// =====================================================================
#define CONV_T 128
#define ICCHUNK 4
#define PSX 22
#define PS (22 * 22)    // 484
#define CONV_SMEM (ICCHUNK * 3 * PS * 8 + ICCHUNK * 27 * 16 * 4)

__global__ __launch_bounds__(CONV_T) void conv_qkv_kernel(
    const float* __restrict__ x,
    const float* __restrict__ wq, const float* __restrict__ bq,
    const float* __restrict__ wk, const float* __restrict__ bk,
    const float* __restrict__ wv, const float* __restrict__ bv)
{
    extern __shared__ __align__(16) char csm[];
    ull*   slab2 = (ull*)csm;                                 // [ic][zz][484] pairs
    float* wsm   = (float*)(csm + ICCHUNK * 3 * PS * 8);      // [ic][27][16]

    const int g = blockIdx.x;
    const int z = blockIdx.y;
    const int b = blockIdx.z;
    const int tid = threadIdx.x;
    const int ocbase = g * 16;

    // voxel coords for 4 slots (slot q -> voxel tid + q*128, clamp inactive)
    int voff[4]; bool act[4];
#pragma unroll
    for (int q = 0; q < 4; ++q) {
        int v = tid + q * CONV_T;
        act[q] = (v < 400);
        int vc = act[q] ? v : 0;
        voff[q] = (vc / 20) * PSX + (vc % 20);   // slab base offset (padded +1,+1 cancels)
    }

    ull acc[4][8];
#pragma unroll
    for (int o2 = 0; o2 < 8; ++o2) {
        int oc0 = ocbase + 2 * o2, oc1 = oc0 + 1;
        float b0 = (oc0 < 8) ? bq[oc0] : (oc0 < 16 ? bk[oc0 - 8] : bv[oc0 - 16]);
        float b1 = (oc1 < 8) ? bq[oc1] : (oc1 < 16 ? bk[oc1 - 8] : bv[oc1 - 16]);
        ull bb = pack2(b0, b1);
#pragma unroll
        for (int q = 0; q < 4; ++q) acc[q][o2] = bb;
    }

    for (int chunk = 0; chunk < CIN / ICCHUNK; ++chunk) {
        __syncthreads();
        // fill duplicated slab (zero borders)
        for (int idx = tid; idx < ICCHUNK * 3 * PS; idx += CONV_T) {
            int spl = idx % PS;
            int zz = (idx / PS) % 3;
            int ic = idx / (3 * PS);
            int yy = spl / PSX - 1;
            int xx = spl % PSX - 1;
            int zg = z + zz - 1;
            float v = 0.f;
            if ((unsigned)zg < 20u && (unsigned)yy < 20u && (unsigned)xx < 20u)
                v = x[(((size_t)b * 64 + chunk * ICCHUNK + ic) * 20 + zg) * 400 + yy * 20 + xx];
            slab2[idx] = dup2(v);
        }
        // fill weights [ic][tap][ocl]  (oc pairs contiguous for f32x2)
        for (int idx = tid; idx < ICCHUNK * 27 * 16; idx += CONV_T) {
            int ocl = idx & 15;
            int tap = (idx >> 4) % 27;
            int ic = idx / (27 * 16);
            int oc = ocbase + ocl;
            int icg = chunk * ICCHUNK + ic;
            float w;
            if (oc < 8)       w = wq[((size_t)oc * 64 + icg) * 27 + tap];
            else if (oc < 16) w = wk[((size_t)(oc - 8) * 64 + icg) * 27 + tap];
            else              w = wv[((size_t)(oc - 16) * 64 + icg) * 27 + tap];
            wsm[idx] = w;
        }
        __syncthreads();

#pragma unroll
        for (int ic = 0; ic < ICCHUNK; ++ic) {
#pragma unroll
            for (int dz = 0; dz < 3; ++dz) {
                const ull* sl = &slab2[(ic * 3 + dz) * PS];
#pragma unroll
                for (int t9 = 0; t9 < 9; ++t9) {
                    const int dy = t9 / 3, dx = t9 % 3;
                    const ull* wp = (const ull*)&wsm[(ic * 27 + dz * 9 + t9) * 16];
                    ull w[8];
#pragma unroll
                    for (int o2 = 0; o2 < 8; ++o2) w[o2] = wp[o2];
#pragma unroll
                    for (int q = 0; q < 4; ++q) {
                        ull xd = sl[voff[q] + dy * PSX + dx];
#pragma unroll
                        for (int o2 = 0; o2 < 8; ++o2) fma2(acc[q][o2], w[o2], xd);
                    }
                }
            }
        }
    }

    // vectorized stores: thread owns 16 consecutive channels per voxel
#pragma unroll
    for (int q = 0; q < 4; ++q) {
        if (!act[q]) continue;
        int v = tid + q * CONV_T;
        int i = z * 400 + v;
        if (g == 0) {
            float4* qd = (float4*)(g_Q + ((size_t)b * N_SPAT + i) * DQK);
            qd[0] = make_float4(lo32(acc[q][0]), hi32(acc[q][0]), lo32(acc[q][1]), hi32(acc[q][1]));
            qd[1] = make_float4(lo32(acc[q][2]), hi32(acc[q][2]), lo32(acc[q][3]), hi32(acc[q][3]));
            float4* kd = (float4*)(g_K + ((size_t)b * N_SPAT + i) * DQK);
            kd[0] = make_float4(lo32(acc[q][4]), hi32(acc[q][4]), lo32(acc[q][5]), hi32(acc[q][5]));
            kd[1] = make_float4(lo32(acc[q][6]), hi32(acc[q][6]), lo32(acc[q][7]), hi32(acc[q][7]));
        } else {
            float4* vd = (float4*)(g_V + ((size_t)b * N_SPAT + i) * DV + (g - 1) * 16);
#pragma unroll
            for (int p = 0; p < 4; ++p)
                vd[p] = make_float4(lo32(acc[q][2 * p]), hi32(acc[q][2 * p]),
                                    lo32(acc[q][2 * p + 1]), hi32(acc[q][2 * p + 1]));
        }
    }
}

// =====================================================================
// Flash attention kernel (split-KV partials). Unchanged from R5 (passing).
// BM=64 rows/CTA, 64 threads, 8x8 micro-tile, grid (125,2,JSPLIT)=1000.
// =====================================================================
#define BM 64
#define BN 64
#define ATT_T 64

__global__ __launch_bounds__(ATT_T, 4) void attn_kernel()
{
    __shared__ __align__(16) float sQT[DQK][BM];       // Q^T, pre-scaled log2(e)
    __shared__ __align__(16) float sKT[2][DQK][BN];    // K^T per buffer
    __shared__ __align__(16) float sV[2][BN][DV];      // V rows per buffer

    const int b = blockIdx.y;
    const int sp = blockIdx.z;
    const int i0 = blockIdx.x * BM;
    const int tid = threadIdx.x;
    const int tc = tid & 7;
    const int tr = tid >> 3;         // 0..7, rows 8tr..8tr+7
    const int lane = tid & 31;

    const int NTALL = N_SPAT / BN;   // 125
    const int t0 = (sp * NTALL) / JSPLIT;
    const int t1 = ((sp + 1) * NTALL) / JSPLIT;

    const float* Qb = g_Q + (size_t)b * N_SPAT * DQK;
    const float* Kb = g_K + (size_t)b * N_SPAT * DQK;
    const float* Vb = g_V + (size_t)b * N_SPAT * DV;

    // ---- load Q tile (row per thread), transpose, pre-scale ----
    {
        const float4* qp = (const float4*)(Qb + (size_t)(i0 + tid) * DQK);
        float4 q0 = qp[0], q1 = qp[1];
        sQT[0][tid] = q0.x * LOG2E_F; sQT[1][tid] = q0.y * LOG2E_F;
        sQT[2][tid] = q0.z * LOG2E_F; sQT[3][tid] = q0.w * LOG2E_F;
        sQT[4][tid] = q1.x * LOG2E_F; sQT[5][tid] = q1.y * LOG2E_F;
        sQT[6][tid] = q1.z * LOG2E_F; sQT[7][tid] = q1.w * LOG2E_F;
    }

    float m[8], l[8];
    ull o[8][4];
#pragma unroll
    for (int ii = 0; ii < 8; ++ii) {
        m[ii] = -CUDART_INF_F;
        l[ii] = 0.f;
#pragma unroll
        for (int c2 = 0; c2 < 4; ++c2) o[ii][c2] = 0ull;
    }

    // ---- prologue: stage tile t0 into buffer 0 ----
    {
        const float* ksrc = Kb + (size_t)t0 * BN * DQK;
        float4 k0 = ((const float4*)ksrc)[2 * tid];
        float4 k1 = ((const float4*)ksrc)[2 * tid + 1];
        const float* vsrc = Vb + (size_t)t0 * BN * DV;
#pragma unroll
        for (int q = 0; q < 16; ++q)
            cp_async16(&((float*)sV[0])[(tid + q * 64) * 4], vsrc + (size_t)(tid + q * 64) * 4);
        cp_commit();
        sKT[0][0][tid] = k0.x; sKT[0][1][tid] = k0.y;
        sKT[0][2][tid] = k0.z; sKT[0][3][tid] = k0.w;
        sKT[0][4][tid] = k1.x; sKT[0][5][tid] = k1.y;
        sKT[0][6][tid] = k1.z; sKT[0][7][tid] = k1.w;
        cp_wait0();
        __syncthreads();
    }

    for (int it = t0; it < t1; ++it) {
        const int cur = (it - t0) & 1;
        const int nxt = cur ^ 1;
        const bool pref = (it + 1 < t1);
        float4 k0r, k1r;
        if (pref) {
            const float* ksrc = Kb + (size_t)(it + 1) * BN * DQK;
            k0r = ((const float4*)ksrc)[2 * tid];
            k1r = ((const float4*)ksrc)[2 * tid + 1];
            const float* vsrc = Vb + (size_t)(it + 1) * BN * DV;
#pragma unroll
            for (int q = 0; q < 16; ++q)
                cp_async16(&((float*)sV[nxt])[(tid + q * 64) * 4], vsrc + (size_t)(tid + q * 64) * 4);
            cp_commit();
        }

        // ---- phase A: S = Q K^T (8x8 micro-tile, k=8) ----
        float s[8][8];
#pragma unroll
        for (int ii = 0; ii < 8; ++ii)
#pragma unroll
            for (int jj = 0; jj < 8; ++jj) s[ii][jj] = 0.f;

#pragma unroll
        for (int k = 0; k < DQK; ++k) {
            float4 qa = *(const float4*)&sQT[k][8 * tr];
            float4 qb = *(const float4*)&sQT[k][8 * tr + 4];
            float4 ka = *(const float4*)&sKT[cur][k][8 * tc];
            float4 kb = *(const float4*)&sKT[cur][k][8 * tc + 4];
            float qv[8] = {qa.x, qa.y, qa.z, qa.w, qb.x, qb.y, qb.z, qb.w};
            float kv[8] = {ka.x, ka.y, ka.z, ka.w, kb.x, kb.y, kb.z, kb.w};
#pragma unroll
            for (int ii = 0; ii < 8; ++ii)
#pragma unroll
                for (int jj = 0; jj < 8; ++jj)
                    s[ii][jj] = fmaf(qv[ii], kv[jj], s[ii][jj]);
        }

        // ---- online softmax (base-2 domain) ----
#pragma unroll
        for (int ii = 0; ii < 8; ++ii) {
            float mx = s[ii][0];
#pragma unroll
            for (int jj = 1; jj < 8; ++jj) mx = fmaxf(mx, s[ii][jj]);
            mx = fmaxf(mx, __shfl_xor_sync(0xffffffffu, mx, 1));
            mx = fmaxf(mx, __shfl_xor_sync(0xffffffffu, mx, 2));
            mx = fmaxf(mx, __shfl_xor_sync(0xffffffffu, mx, 4));
            float mnew = fmaxf(m[ii], mx);
            float alpha = exp2f(m[ii] - mnew);
            m[ii] = mnew;
            float rs = 0.f;
#pragma unroll
            for (int jj = 0; jj < 8; ++jj) {
                float p = exp2f(s[ii][jj] - mnew);
                s[ii][jj] = p;          // s now holds P
                rs += p;
            }
            rs += __shfl_xor_sync(0xffffffffu, rs, 1);
            rs += __shfl_xor_sync(0xffffffffu, rs, 2);
            rs += __shfl_xor_sync(0xffffffffu, rs, 4);
            l[ii] = l[ii] * alpha + rs;
            ull a2 = dup2(alpha);
#pragma unroll
            for (int c2 = 0; c2 < 4; ++c2) o[ii][c2] = mul2(o[ii][c2], a2);
        }

        // ---- phase C: O += P @ V  (P broadcast via shuffle, FFMA2) ----
#pragma unroll
        for (int ko = 0; ko < 8; ++ko) {
#pragma unroll
            for (int jj = 0; jj < 8; ++jj) {
                int k = ko * 8 + jj;
                const ulonglong2* vp = (const ulonglong2*)&sV[cur][k][8 * tc];
                ulonglong2 v01 = vp[0];
                ulonglong2 v23 = vp[1];
                int srcLane = (lane & 24) | ko;
#pragma unroll
                for (int ii = 0; ii < 8; ++ii) {
                    float pv = __shfl_sync(0xffffffffu, s[ii][jj], srcLane);
                    ull pd = dup2(pv);
                    fma2(o[ii][0], v01.x, pd);
                    fma2(o[ii][1], v01.y, pd);
                    fma2(o[ii][2], v23.x, pd);
                    fma2(o[ii][3], v23.y, pd);
                }
            }
        }

        if (pref) {
            sKT[nxt][0][tid] = k0r.x; sKT[nxt][1][tid] = k0r.y;
            sKT[nxt][2][tid] = k0r.z; sKT[nxt][3][tid] = k0r.w;
            sKT[nxt][4][tid] = k1r.x; sKT[nxt][5][tid] = k1r.y;
            sKT[nxt][6][tid] = k1r.z; sKT[nxt][7][tid] = k1r.w;
        }
        cp_wait0();
        __syncthreads();
    }

    // ---- epilogue: write unnormalized partials + (m,l) ----
    const size_t sb = (size_t)(sp * 2 + b);
#pragma unroll
    for (int ii = 0; ii < 8; ++ii) {
        int i = i0 + 8 * tr + ii;
        float* dst = g_Opart + (sb * N_SPAT + i) * DV + 8 * tc;
        ((float4*)dst)[0] = make_float4(lo32(o[ii][0]), hi32(o[ii][0]),
                                        lo32(o[ii][1]), hi32(o[ii][1]));
        ((float4*)dst)[1] = make_float4(lo32(o[ii][2]), hi32(o[ii][2]),
                                        lo32(o[ii][3]), hi32(o[ii][3]));
        if (tc == 0) {
            g_m[sb * N_SPAT + i] = m[ii];
            g_l[sb * N_SPAT + i] = l[ii];
        }
    }
}

// =====================================================================
// Merge kernel: combine JSPLIT partials (log-sum-exp, base-2 domain),
// transpose via smem, coalesced out[b][c][i] writes.
// =====================================================================
__global__ __launch_bounds__(256) void merge_kernel(float* __restrict__ out)
{
    __shared__ float T[DV][65];   // [c][i_local]

    const int b = blockIdx.y;
    const int i0 = blockIdx.x * 64;
    const int tid = threadIdx.x;
    const int il = tid >> 2;          // 0..63
    const int cq = tid & 3;           // channel quad group
    const int i = i0 + il;

    float mm[JSPLIT], coef[JSPLIT];
    float mstar = -CUDART_INF_F;
#pragma unroll
    for (int s = 0; s < JSPLIT; ++s) {
        mm[s] = g_m[((size_t)(s * 2 + b)) * N_SPAT + i];
        mstar = fmaxf(mstar, mm[s]);
    }
    float denom = 0.f;
#pragma unroll
    for (int s = 0; s < JSPLIT; ++s) {
        coef[s] = exp2f(mm[s] - mstar);
        denom += coef[s] * g_l[((size_t)(s * 2 + b)) * N_SPAT + i];
    }
    const float inv = 1.0f / denom;

    float acc[16];
#pragma unroll
    for (int e = 0; e < 16; ++e) acc[e] = 0.f;
#pragma unroll
    for (int s = 0; s < JSPLIT; ++s) {
        const float4* src = (const float4*)(g_Opart +
            (((size_t)(s * 2 + b)) * N_SPAT + i) * DV + cq * 16);
        float c = coef[s];
#pragma unroll
        for (int q = 0; q < 4; ++q) {
            float4 f = src[q];
            acc[4 * q + 0] = fmaf(c, f.x, acc[4 * q + 0]);
            acc[4 * q + 1] = fmaf(c, f.y, acc[4 * q + 1]);
            acc[4 * q + 2] = fmaf(c, f.z, acc[4 * q + 2]);
            acc[4 * q + 3] = fmaf(c, f.w, acc[4 * q + 3]);
        }
    }
#pragma unroll
    for (int e = 0; e < 16; ++e) T[cq * 16 + e][il] = acc[e] * inv;
    __syncthreads();

    {
        const int c = tid >> 2;
        const int ich = (tid & 3) * 16;
        float* dst = out + ((size_t)b * DV + c) * N_SPAT + i0 + ich;
#pragma unroll
        for (int q = 0; q < 4; ++q)
            ((float4*)dst)[q] = make_float4(T[c][ich + 4 * q + 0], T[c][ich + 4 * q + 1],
                                            T[c][ich + 4 * q + 2], T[c][ich + 4 * q + 3]);
    }
}

// =====================================================================
extern "C" void kernel_launch(void* const* d_in, const int* in_sizes, int n_in,
                              void* d_out, int out_size)
{
    const float* x  = (const float*)d_in[0];
    const float* wq = (const float*)d_in[1];
    const float* bq = (const float*)d_in[2];
    const float* wk = (const float*)d_in[3];
    const float* bk = (const float*)d_in[4];
    const float* wv = (const float*)d_in[5];
    const float* bv = (const float*)d_in[6];
    float* out = (float*)d_out;

    cudaFuncSetAttribute(conv_qkv_kernel,
                         cudaFuncAttributeMaxDynamicSharedMemorySize,
                         CONV_SMEM);

    dim3 cgrid(5, 20, 2);                 // ocGroup, z, batch
    conv_qkv_kernel<<<cgrid, CONV_T, CONV_SMEM>>>(x, wq, bq, wk, bk, wv, bv);

    dim3 agrid(N_SPAT / BM, 2, JSPLIT);   // 125 x 2 x 4 = 1000 CTAs
    attn_kernel<<<agrid, ATT_T>>>();

    dim3 mgrid(N_SPAT / 64, 2);
    merge_kernel<<<mgrid, 256>>>(out);
}

// round 7
// speedup vs baseline: 1.4466x; 1.4466x over previous
#include <cuda_runtime.h>
#include <math_constants.h>

#define N_SPAT 8000
#define CIN 64
#define DQK 8
#define DV 64
#define LOG2E_F 1.4426950408889634f
#define JSPLIT 4

typedef unsigned long long ull;

// ---------------- scratch (no allocations allowed) ----------------
__device__ float g_Q[2 * N_SPAT * DQK];             // [b][i][c8]
__device__ float g_K[2 * N_SPAT * DQK];             // [b][j][c8]
__device__ float g_V[2 * N_SPAT * DV];              // [b][j][c64]
__device__ float g_Qp[2 * 2 * N_SPAT * DQK];        // [ichalf][b][i][c8]
__device__ float g_Kp[2 * 2 * N_SPAT * DQK];
__device__ float g_Vp[2 * 2 * N_SPAT * DV];
__device__ float g_Opart[JSPLIT * 2 * N_SPAT * DV]; // [s][b][i][c]
__device__ float g_m[JSPLIT * 2 * N_SPAT];
__device__ float g_l[JSPLIT * 2 * N_SPAT];

// ---------------- f32x2 helpers (FFMA2 path, sm_10x) ----------------
__device__ __forceinline__ ull dup2(float x) {
    ull r;
    asm("mov.b64 %0, {%1, %1};" : "=l"(r) : "r"(__float_as_uint(x)));
    return r;
}
__device__ __forceinline__ ull pack2(float lo, float hi) {
    ull r;
    asm("mov.b64 %0, {%1, %2};" : "=l"(r) : "r"(__float_as_uint(lo)), "r"(__float_as_uint(hi)));
    return r;
}
__device__ __forceinline__ void fma2(ull& d, ull a, ull b) {
    asm("fma.rn.f32x2 %0, %1, %2, %0;" : "+l"(d) : "l"(a), "l"(b));
}
__device__ __forceinline__ ull mul2(ull a, ull b) {
    ull r;
    asm("mul.rn.f32x2 %0, %1, %2;" : "=l"(r) : "l"(a), "l"(b));
    return r;
}
__device__ __forceinline__ float lo32(ull v) { return __uint_as_float((unsigned)v); }
__device__ __forceinline__ float hi32(ull v) { return __uint_as_float((unsigned)(v >> 32)); }

// store {a,a,b,b} (two duplicated f32 pairs) with NO extra MOVs
__device__ __forceinline__ void sts_dupdup(unsigned addr, float a, float b) {
    asm volatile("st.shared.v4.f32 [%0], {%1,%1,%2,%2};"
                 :: "r"(addr), "f"(a), "f"(b) : "memory");
}

// ---------------- cp.async helpers ----------------
__device__ __forceinline__ void cp_async16(void* smem, const void* gmem) {
    unsigned saddr = (unsigned)__cvta_generic_to_shared(smem);
    asm volatile("cp.async.cg.shared.global [%0], [%1], 16;\n" :: "r"(saddr), "l"(gmem));
}
__device__ __forceinline__ void cp_commit() { asm volatile("cp.async.commit_group;\n"); }
__device__ __forceinline__ void cp_wait0() { asm volatile("cp.async.wait_group 0;\n"); }

// =====================================================================
// Conv kernel: fused Q/K/V 3x3x3 SAME conv, ic-split + x-pair voxels.
// Grid (5 ocGroups, 20 z, 4 = ih*2+b), block 200.
// Thread owns voxels (y, 2xp) and (y, 2xp+1); per (ic,dz,dy) a 4-float
// slab window (2 LDS.64) serves all 3 dx taps for BOTH voxels.
// Each ic-half writes partial outputs; combine_kernel sums halves.
// =====================================================================
#define CONV_T 200
#define ICCHUNK 4
#define PSX 22
#define PS (22 * 22)    // padded full plane

__global__ __launch_bounds__(CONV_T) void conv_qkv_kernel(
    const float* __restrict__ x,
    const float* __restrict__ wq, const float* __restrict__ bq,
    const float* __restrict__ wk, const float* __restrict__ bk,
    const float* __restrict__ wv, const float* __restrict__ bv)
{
    __shared__ __align__(16) float slab[ICCHUNK][3][PS];
    __shared__ __align__(16) float wsm[ICCHUNK * 27 * 16];

    const int g = blockIdx.x;
    const int z = blockIdx.y;
    const int b = blockIdx.z & 1;
    const int ih = blockIdx.z >> 1;          // ic half
    const int tid = threadIdx.x;             // 0..199
    const int y = tid / 10;                  // 0..19
    const int xp = tid % 10;                 // x-pair index
    const int ocbase = g * 16;

    ull acc0[8], acc1[8];
#pragma unroll
    for (int o2 = 0; o2 < 8; ++o2) {
        ull bb = 0ull;
        if (ih == 0) {
            int oc0 = ocbase + 2 * o2, oc1 = oc0 + 1;
            float b0 = (oc0 < 8) ? bq[oc0] : (oc0 < 16 ? bk[oc0 - 8] : bv[oc0 - 16]);
            float b1 = (oc1 < 8) ? bq[oc1] : (oc1 < 16 ? bk[oc1 - 8] : bv[oc1 - 16]);
            bb = pack2(b0, b1);
        }
        acc0[o2] = bb; acc1[o2] = bb;
    }

    for (int chunk = 0; chunk < 32 / ICCHUNK; ++chunk) {
        const int icbase = ih * 32 + chunk * ICCHUNK;
        __syncthreads();
        // fill padded slab (zero borders)
        for (int idx = tid; idx < ICCHUNK * 3 * PS; idx += CONV_T) {
            int spl = idx % PS;
            int zz = (idx / PS) % 3;
            int ic = idx / (3 * PS);
            int yy = spl / PSX - 1;
            int xx = spl % PSX - 1;
            int zg = z + zz - 1;
            float v = 0.f;
            if ((unsigned)zg < 20u && (unsigned)yy < 20u && (unsigned)xx < 20u)
                v = x[(((size_t)b * 64 + icbase + ic) * 20 + zg) * 400 + yy * 20 + xx];
            slab[ic][zz][spl] = v;
        }
        // fill weights [ic][tap][ocl] (oc pairs contiguous for f32x2)
        for (int idx = tid; idx < ICCHUNK * 27 * 16; idx += CONV_T) {
            int ocl = idx & 15;
            int tap = (idx >> 4) % 27;
            int ic = idx / (27 * 16);
            int oc = ocbase + ocl;
            int icg = icbase + ic;
            float w;
            if (oc < 8)       w = wq[((size_t)oc * 64 + icg) * 27 + tap];
            else if (oc < 16) w = wk[((size_t)(oc - 8) * 64 + icg) * 27 + tap];
            else              w = wv[((size_t)(oc - 16) * 64 + icg) * 27 + tap];
            wsm[idx] = w;
        }
        __syncthreads();

#pragma unroll
        for (int ic = 0; ic < ICCHUNK; ++ic) {
#pragma unroll
            for (int dz = 0; dz < 3; ++dz) {
#pragma unroll
                for (int dy = 0; dy < 3; ++dy) {
                    // 4-float window (aligned: 22*(y+dy) and 2*xp both even)
                    const float* wbase = &slab[ic][dz][(y + dy) * PSX + 2 * xp];
                    float2 wlo = *(const float2*)wbase;
                    float2 whi = *(const float2*)(wbase + 2);
                    ull d0 = dup2(wlo.x), d1 = dup2(wlo.y);
                    ull d2 = dup2(whi.x), d3 = dup2(whi.y);
                    ull dv[4] = {d0, d1, d2, d3};
#pragma unroll
                    for (int dx = 0; dx < 3; ++dx) {
                        const ull* wp = (const ull*)&wsm[(ic * 27 + dz * 9 + dy * 3 + dx) * 16];
                        ull w[8];
#pragma unroll
                        for (int o2 = 0; o2 < 8; ++o2) w[o2] = wp[o2];
#pragma unroll
                        for (int o2 = 0; o2 < 8; ++o2) {
                            fma2(acc0[o2], w[o2], dv[dx]);
                            fma2(acc1[o2], w[o2], dv[dx + 1]);
                        }
                    }
                }
            }
        }
    }

    // stores: thread owns 16 consecutive channels for 2 voxels
    const int i0v = z * 400 + y * 20 + 2 * xp;
    const size_t hb = (size_t)(ih * 2 + b);
#pragma unroll
    for (int q = 0; q < 2; ++q) {
        ull* a = q ? acc1 : acc0;
        int i = i0v + q;
        if (g == 0) {
            float4* qd = (float4*)(g_Qp + (hb * N_SPAT + i) * DQK);
            qd[0] = make_float4(lo32(a[0]), hi32(a[0]), lo32(a[1]), hi32(a[1]));
            qd[1] = make_float4(lo32(a[2]), hi32(a[2]), lo32(a[3]), hi32(a[3]));
            float4* kd = (float4*)(g_Kp + (hb * N_SPAT + i) * DQK);
            kd[0] = make_float4(lo32(a[4]), hi32(a[4]), lo32(a[5]), hi32(a[5]));
            kd[1] = make_float4(lo32(a[6]), hi32(a[6]), lo32(a[7]), hi32(a[7]));
        } else {
            float4* vd = (float4*)(g_Vp + (hb * N_SPAT + i) * DV + (g - 1) * 16);
#pragma unroll
            for (int p = 0; p < 4; ++p)
                vd[p] = make_float4(lo32(a[2 * p]), hi32(a[2 * p]),
                                    lo32(a[2 * p + 1]), hi32(a[2 * p + 1]));
        }
    }
}

// =====================================================================
// Combine kernel: g_X = g_Xp[half0] + g_Xp[half1]  (float4 lanes)
// Q:[0,32000) K:[32000,64000) V:[64000,320000) float4 units
// =====================================================================
__global__ __launch_bounds__(256) void combine_kernel()
{
    int idx = blockIdx.x * 256 + threadIdx.x;
    if (idx < 32000) {
        const float4* s = (const float4*)g_Qp;
        float4 a = s[idx], c = s[idx + 32000];
        ((float4*)g_Q)[idx] = make_float4(a.x + c.x, a.y + c.y, a.z + c.z, a.w + c.w);
    } else if (idx < 64000) {
        int t = idx - 32000;
        const float4* s = (const float4*)g_Kp;
        float4 a = s[t], c = s[t + 32000];
        ((float4*)g_K)[t] = make_float4(a.x + c.x, a.y + c.y, a.z + c.z, a.w + c.w);
    } else {
        int t = idx - 64000;
        const float4* s = (const float4*)g_Vp;
        float4 a = s[t], c = s[t + 256000];
        ((float4*)g_V)[t] = make_float4(a.x + c.x, a.y + c.y, a.z + c.z, a.w + c.w);
    }
}

// =====================================================================
// Flash attention kernel (split-KV partials).
// BM=64 rows/CTA, 64 threads, 8x8 micro-tile, grid (125,2,JSPLIT)=1000.
// NEW: P exchanged via pre-duplicated smem pairs (st.shared.v4 {p,p,q,q});
// phase C uses LDS.128 broadcast loads -> no SHFL, no dup MOVs.
// Dynamic smem (floats): sQT[8][64]@0, sKT[2][8][64]@512,
//   sV[2][64][64]@1536, sPd[64][64] (ull)@9728 -> 71680 B total.
// =====================================================================
#define BM 64
#define BN 64
#define ATT_T 64
#define ATT_SMEM 71680

__global__ __launch_bounds__(ATT_T, 3) void attn_kernel()
{
    extern __shared__ __align__(16) float dyn[];
    float* sQT = dyn;                 // [k][i]
    float* sKT = dyn + 512;           // [buf][k][j]
    float* sV  = dyn + 1536;          // [buf][j][c], buffer stride 4096
    ull*   sPd = (ull*)(dyn + 9728);  // [row][k] duplicated pairs

    const int b = blockIdx.y;
    const int sp = blockIdx.z;
    const int i0 = blockIdx.x * BM;
    const int tid = threadIdx.x;
    const int tc = tid & 7;
    const int tr = tid >> 3;         // 0..7, rows 8tr..8tr+7

    const unsigned spd_base = (unsigned)__cvta_generic_to_shared(sPd);

    const int NTALL = N_SPAT / BN;   // 125
    const int t0 = (sp * NTALL) / JSPLIT;
    const int t1 = ((sp + 1) * NTALL) / JSPLIT;

    const float* Qb = g_Q + (size_t)b * N_SPAT * DQK;
    const float* Kb = g_K + (size_t)b * N_SPAT * DQK;
    const float* Vb = g_V + (size_t)b * N_SPAT * DV;

    // ---- load Q tile (row per thread), transpose, pre-scale ----
    {
        const float4* qp = (const float4*)(Qb + (size_t)(i0 + tid) * DQK);
        float4 q0 = qp[0], q1 = qp[1];
        sQT[0 * 64 + tid] = q0.x * LOG2E_F; sQT[1 * 64 + tid] = q0.y * LOG2E_F;
        sQT[2 * 64 + tid] = q0.z * LOG2E_F; sQT[3 * 64 + tid] = q0.w * LOG2E_F;
        sQT[4 * 64 + tid] = q1.x * LOG2E_F; sQT[5 * 64 + tid] = q1.y * LOG2E_F;
        sQT[6 * 64 + tid] = q1.z * LOG2E_F; sQT[7 * 64 + tid] = q1.w * LOG2E_F;
    }

    float m[8], l[8];
    ull o[8][4];
#pragma unroll
    for (int ii = 0; ii < 8; ++ii) {
        m[ii] = -CUDART_INF_F;
        l[ii] = 0.f;
#pragma unroll
        for (int c2 = 0; c2 < 4; ++c2) o[ii][c2] = 0ull;
    }

    // ---- prologue: stage tile t0 into buffer 0 ----
    {
        const float* ksrc = Kb + (size_t)t0 * BN * DQK;
        float4 k0 = ((const float4*)ksrc)[2 * tid];
        float4 k1 = ((const float4*)ksrc)[2 * tid + 1];
        const float* vsrc = Vb + (size_t)t0 * BN * DV;
#pragma unroll
        for (int q = 0; q < 16; ++q)
            cp_async16(&sV[(tid + q * 64) * 4], vsrc + (size_t)(tid + q * 64) * 4);
        cp_commit();
        sKT[0 * 64 + tid] = k0.x; sKT[1 * 64 + tid] = k0.y;
        sKT[2 * 64 + tid] = k0.z; sKT[3 * 64 + tid] = k0.w;
        sKT[4 * 64 + tid] = k1.x; sKT[5 * 64 + tid] = k1.y;
        sKT[6 * 64 + tid] = k1.z; sKT[7 * 64 + tid] = k1.w;
        cp_wait0();
        __syncthreads();
    }

    for (int it = t0; it < t1; ++it) {
        const int cur = (it - t0) & 1;
        const int nxt = cur ^ 1;
        const bool pref = (it + 1 < t1);
        float4 k0r, k1r;
        if (pref) {
            const float* ksrc = Kb + (size_t)(it + 1) * BN * DQK;
            k0r = ((const float4*)ksrc)[2 * tid];
            k1r = ((const float4*)ksrc)[2 * tid + 1];
            const float* vsrc = Vb + (size_t)(it + 1) * BN * DV;
#pragma unroll
            for (int q = 0; q < 16; ++q)
                cp_async16(&sV[nxt * 4096 + (tid + q * 64) * 4],
                           vsrc + (size_t)(tid + q * 64) * 4);
            cp_commit();
        }

        // ---- phase A: S = Q K^T (8x8 micro-tile, k=8) ----
        float s[8][8];
#pragma unroll
        for (int ii = 0; ii < 8; ++ii)
#pragma unroll
            for (int jj = 0; jj < 8; ++jj) s[ii][jj] = 0.f;

#pragma unroll
        for (int k = 0; k < DQK; ++k) {
            float4 qa = *(const float4*)&sQT[k * 64 + 8 * tr];
            float4 qb = *(const float4*)&sQT[k * 64 + 8 * tr + 4];
            float4 ka = *(const float4*)&sKT[cur * 512 + k * 64 + 8 * tc];
            float4 kb = *(const float4*)&sKT[cur * 512 + k * 64 + 8 * tc + 4];
            float qv[8] = {qa.x, qa.y, qa.z, qa.w, qb.x, qb.y, qb.z, qb.w};
            float kv[8] = {ka.x, ka.y, ka.z, ka.w, kb.x, kb.y, kb.z, kb.w};
#pragma unroll
            for (int ii = 0; ii < 8; ++ii)
#pragma unroll
                for (int jj = 0; jj < 8; ++jj)
                    s[ii][jj] = fmaf(qv[ii], kv[jj], s[ii][jj]);
        }

        // ---- online softmax (base-2) + publish P duplicated ----
#pragma unroll
        for (int ii = 0; ii < 8; ++ii) {
            float mx = s[ii][0];
#pragma unroll
            for (int jj = 1; jj < 8; ++jj) mx = fmaxf(mx, s[ii][jj]);
            mx = fmaxf(mx, __shfl_xor_sync(0xffffffffu, mx, 1));
            mx = fmaxf(mx, __shfl_xor_sync(0xffffffffu, mx, 2));
            mx = fmaxf(mx, __shfl_xor_sync(0xffffffffu, mx, 4));
            float mnew = fmaxf(m[ii], mx);
            float alpha = exp2f(m[ii] - mnew);
            m[ii] = mnew;
            float rs = 0.f;
#pragma unroll
            for (int jj = 0; jj < 8; ++jj) {
                float p = exp2f(s[ii][jj] - mnew);
                s[ii][jj] = p;
                rs += p;
            }
            rs += __shfl_xor_sync(0xffffffffu, rs, 1);
            rs += __shfl_xor_sync(0xffffffffu, rs, 2);
            rs += __shfl_xor_sync(0xffffffffu, rs, 4);
            l[ii] = l[ii] * alpha + rs;
            ull a2 = dup2(alpha);
#pragma unroll
            for (int c2 = 0; c2 < 4; ++c2) o[ii][c2] = mul2(o[ii][c2], a2);
            // write P row segment as duplicated pairs (no MOVs)
            unsigned addr = spd_base + (((8 * tr + ii) * 64 + 8 * tc) << 3);
#pragma unroll
            for (int q = 0; q < 4; ++q)
                sts_dupdup(addr + (q << 4), s[ii][2 * q], s[ii][2 * q + 1]);
        }
        __syncwarp();   // P rows produced/consumed within the same warp

        // ---- phase C: O += P @ V (broadcast LDS.128, FFMA2) ----
        {
            const float* vbase = sV + cur * 4096;
#pragma unroll 2
            for (int kp = 0; kp < 32; ++kp) {
                const int k0 = 2 * kp;
                const ulonglong2* vpa = (const ulonglong2*)&vbase[k0 * 64 + 8 * tc];
                ulonglong2 va0 = vpa[0], va1 = vpa[1];
                const ulonglong2* vpb = (const ulonglong2*)&vbase[(k0 + 1) * 64 + 8 * tc];
                ulonglong2 vb0 = vpb[0], vb1 = vpb[1];
#pragma unroll
                for (int ii = 0; ii < 8; ++ii) {
                    ulonglong2 pp = *(const ulonglong2*)&sPd[(8 * tr + ii) * 64 + k0];
                    fma2(o[ii][0], va0.x, pp.x);
                    fma2(o[ii][1], va0.y, pp.x);
                    fma2(o[ii][2], va1.x, pp.x);
                    fma2(o[ii][3], va1.y, pp.x);
                    fma2(o[ii][0], vb0.x, pp.y);
                    fma2(o[ii][1], vb0.y, pp.y);
                    fma2(o[ii][2], vb1.x, pp.y);
                    fma2(o[ii][3], vb1.y, pp.y);
                }
            }
        }

        if (pref) {
            float* kt = &sKT[nxt * 512];
            kt[0 * 64 + tid] = k0r.x; kt[1 * 64 + tid] = k0r.y;
            kt[2 * 64 + tid] = k0r.z; kt[3 * 64 + tid] = k0r.w;
            kt[4 * 64 + tid] = k1r.x; kt[5 * 64 + tid] = k1r.y;
            kt[6 * 64 + tid] = k1r.z; kt[7 * 64 + tid] = k1r.w;
        }
        cp_wait0();
        __syncthreads();
    }

    // ---- epilogue: write unnormalized partials + (m,l) ----
    const size_t sb = (size_t)(sp * 2 + b);
#pragma unroll
    for (int ii = 0; ii < 8; ++ii) {
        int i = i0 + 8 * tr + ii;
        float* dst = g_Opart + (sb * N_SPAT + i) * DV + 8 * tc;
        ((float4*)dst)[0] = make_float4(lo32(o[ii][0]), hi32(o[ii][0]),
                                        lo32(o[ii][1]), hi32(o[ii][1]));
        ((float4*)dst)[1] = make_float4(lo32(o[ii][2]), hi32(o[ii][2]),
                                        lo32(o[ii][3]), hi32(o[ii][3]));
        if (tc == 0) {
            g_m[sb * N_SPAT + i] = m[ii];
            g_l[sb * N_SPAT + i] = l[ii];
        }
    }
}

// =====================================================================
// Merge kernel: combine JSPLIT partials (log-sum-exp, base-2 domain),
// transpose via smem, coalesced out[b][c][i] writes.
// =====================================================================
__global__ __launch_bounds__(256) void merge_kernel(float* __restrict__ out)
{
    __shared__ float T[DV][65];   // [c][i_local]

    const int b = blockIdx.y;
    const int i0 = blockIdx.x * 64;
    const int tid = threadIdx.x;
    const int il = tid >> 2;          // 0..63
    const int cq = tid & 3;           // channel quad group
    const int i = i0 + il;

    float mm[JSPLIT], coef[JSPLIT];
    float mstar = -CUDART_INF_F;
#pragma unroll
    for (int s = 0; s < JSPLIT; ++s) {
        mm[s] = g_m[((size_t)(s * 2 + b)) * N_SPAT + i];
        mstar = fmaxf(mstar, mm[s]);
    }
    float denom = 0.f;
#pragma unroll
    for (int s = 0; s < JSPLIT; ++s) {
        coef[s] = exp2f(mm[s] - mstar);
        denom += coef[s] * g_l[((size_t)(s * 2 + b)) * N_SPAT + i];
    }
    const float inv = 1.0f / denom;

    float acc[16];
#pragma unroll
    for (int e = 0; e < 16; ++e) acc[e] = 0.f;
#pragma unroll
    for (int s = 0; s < JSPLIT; ++s) {
        const float4* src = (const float4*)(g_Opart +
            (((size_t)(s * 2 + b)) * N_SPAT + i) * DV + cq * 16);
        float c = coef[s];
#pragma unroll
        for (int q = 0; q < 4; ++q) {
            float4 f = src[q];
            acc[4 * q + 0] = fmaf(c, f.x, acc[4 * q + 0]);
            acc[4 * q + 1] = fmaf(c, f.y, acc[4 * q + 1]);
            acc[4 * q + 2] = fmaf(c, f.z, acc[4 * q + 2]);
            acc[4 * q + 3] = fmaf(c, f.w, acc[4 * q + 3]);
        }
    }
#pragma unroll
    for (int e = 0; e < 16; ++e) T[cq * 16 + e][il] = acc[e] * inv;
    __syncthreads();

    {
        const int c = tid >> 2;
        const int ich = (tid & 3) * 16;
        float* dst = out + ((size_t)b * DV + c) * N_SPAT + i0 + ich;
#pragma unroll
        for (int q = 0; q < 4; ++q)
            ((float4*)dst)[q] = make_float4(T[c][ich + 4 * q + 0], T[c][ich + 4 * q + 1],
                                            T[c][ich + 4 * q + 2], T[c][ich + 4 * q + 3]);
    }
}

// =====================================================================
extern "C" void kernel_launch(void* const* d_in, const int* in_sizes, int n_in,
                              void* d_out, int out_size)
{
    const float* x  = (const float*)d_in[0];
    const float* wq = (const float*)d_in[1];
    const float* bq = (const float*)d_in[2];
    const float* wk = (const float*)d_in[3];
    const float* bk = (const float*)d_in[4];
    const float* wv = (const float*)d_in[5];
    const float* bv = (const float*)d_in[6];
    float* out = (float*)d_out;

    cudaFuncSetAttribute(attn_kernel,
                         cudaFuncAttributeMaxDynamicSharedMemorySize,
                         ATT_SMEM);

    dim3 cgrid(5, 20, 4);                 // ocGroup, z, ih*2+b
    conv_qkv_kernel<<<cgrid, CONV_T>>>(x, wq, bq, wk, bk, wv, bv);

    combine_kernel<<<1250, 256>>>();

    dim3 agrid(N_SPAT / BM, 2, JSPLIT);   // 125 x 2 x 4 = 1000 CTAs
    attn_kernel<<<agrid, ATT_T, ATT_SMEM>>>();

    dim3 mgrid(N_SPAT / 64, 2);
    merge_kernel<<<mgrid, 256>>>(out);
}

// round 8
// speedup vs baseline: 1.6191x; 1.1192x over previous
#include <cuda_runtime.h>
#include <math_constants.h>

#define N_SPAT 8000
#define CIN 64
#define DQK 8
#define DV 64
#define LOG2E_F 1.4426950408889634f
#define JSPLIT 5

typedef unsigned long long ull;

// ---------------- scratch (no allocations allowed) ----------------
__device__ float g_Q[2 * N_SPAT * DQK];             // [b][i][c8]
__device__ float g_K[2 * N_SPAT * DQK];             // [b][j][c8]
__device__ float g_V[2 * N_SPAT * DV];              // [b][j][c64]
__device__ float g_Opart[JSPLIT * 2 * N_SPAT * DV]; // [s][b][i][c]
__device__ float g_m[JSPLIT * 2 * N_SPAT];
__device__ float g_l[JSPLIT * 2 * N_SPAT];

// ---------------- f32x2 helpers (FFMA2 path, sm_10x) ----------------
__device__ __forceinline__ ull dup2(float x) {
    ull r;
    asm("mov.b64 %0, {%1, %1};" : "=l"(r) : "r"(__float_as_uint(x)));
    return r;
}
__device__ __forceinline__ ull pack2(float lo, float hi) {
    ull r;
    asm("mov.b64 %0, {%1, %2};" : "=l"(r) : "r"(__float_as_uint(lo)), "r"(__float_as_uint(hi)));
    return r;
}
__device__ __forceinline__ void fma2(ull& d, ull a, ull b) {
    asm("fma.rn.f32x2 %0, %1, %2, %0;" : "+l"(d) : "l"(a), "l"(b));
}
__device__ __forceinline__ ull mul2(ull a, ull b) {
    ull r;
    asm("mul.rn.f32x2 %0, %1, %2;" : "=l"(r) : "l"(a), "l"(b));
    return r;
}
__device__ __forceinline__ float lo32(ull v) { return __uint_as_float((unsigned)v); }
__device__ __forceinline__ float hi32(ull v) { return __uint_as_float((unsigned)(v >> 32)); }

// ---------------- cp.async helpers ----------------
__device__ __forceinline__ void cp_async16(void* smem, const void* gmem) {
    unsigned saddr = (unsigned)__cvta_generic_to_shared(smem);
    asm volatile("cp.async.cg.shared.global [%0], [%1], 16;\n" :: "r"(saddr), "l"(gmem));
}
__device__ __forceinline__ void cp_commit() { asm volatile("cp.async.commit_group;\n"); }
__device__ __forceinline__ void cp_wait0() { asm volatile("cp.async.wait_group 0;\n"); }

// =====================================================================
// Conv kernel (R5 version, measured 268us): fused Q/K/V 3x3x3 SAME conv.
// Grid (5 ocGroups, 40 = z*2+yhalf, 2 b), block 200 (thread per (y,x)
// in a 10-row half-plane). Padded 12x22 slab, ICCHUNK=8.
// =====================================================================
#define CONV_T 200
#define ICCHUNK 8
#define PSY 12
#define PSX 22
#define PS (PSY * PSX)   // 264

__global__ __launch_bounds__(CONV_T) void conv_qkv_kernel(
    const float* __restrict__ x,
    const float* __restrict__ wq, const float* __restrict__ bq,
    const float* __restrict__ wk, const float* __restrict__ bk,
    const float* __restrict__ wv, const float* __restrict__ bv)
{
    __shared__ __align__(16) float slab[ICCHUNK][3][PS];
    __shared__ __align__(16) float wsm[ICCHUNK][27][16];

    const int g = blockIdx.x;
    const int z = blockIdx.y >> 1;
    const int yh = blockIdx.y & 1;
    const int b = blockIdx.z;
    const int tid = threadIdx.x;           // 0..199
    const int yl = tid / 20;               // 0..9
    const int xc = tid % 20;
    const int yg = yh * 10 + yl;
    const int ocbase = g * 16;

    ull acc[8];
#pragma unroll
    for (int o2 = 0; o2 < 8; ++o2) {
        int oc0 = ocbase + 2 * o2, oc1 = oc0 + 1;
        float b0 = (oc0 < 8) ? bq[oc0] : (oc0 < 16 ? bk[oc0 - 8] : bv[oc0 - 16]);
        float b1 = (oc1 < 8) ? bq[oc1] : (oc1 < 16 ? bk[oc1 - 8] : bv[oc1 - 16]);
        acc[o2] = pack2(b0, b1);
    }

    for (int chunk = 0; chunk < CIN / ICCHUNK; ++chunk) {
        __syncthreads();
        // fill padded input slab (zero borders): rows yh*10-1 .. yh*10+10
        for (int idx = tid; idx < ICCHUNK * 3 * PS; idx += CONV_T) {
            int spl = idx % PS;
            int zz = (idx / PS) % 3;
            int ic = idx / (3 * PS);
            int yy = yh * 10 + spl / PSX - 1;
            int xx = spl % PSX - 1;
            int zg = z + zz - 1;
            float v = 0.f;
            if ((unsigned)zg < 20u && (unsigned)yy < 20u && (unsigned)xx < 20u)
                v = x[(((size_t)b * 64 + chunk * ICCHUNK + ic) * 20 + zg) * 400 + yy * 20 + xx];
            slab[ic][zz][spl] = v;
        }
        // fill weights [ic][tap][ocl]  (oc pairs contiguous for f32x2)
        for (int idx = tid; idx < ICCHUNK * 27 * 16; idx += CONV_T) {
            int ocl = idx & 15;
            int tap = (idx >> 4) % 27;
            int ic = idx / (27 * 16);
            int oc = ocbase + ocl;
            int icg = chunk * ICCHUNK + ic;
            float w;
            if (oc < 8)       w = wq[((size_t)oc * 64 + icg) * 27 + tap];
            else if (oc < 16) w = wk[((size_t)(oc - 8) * 64 + icg) * 27 + tap];
            else              w = wv[((size_t)(oc - 16) * 64 + icg) * 27 + tap];
            wsm[ic][tap][ocl] = w;
        }
        __syncthreads();

#pragma unroll 2
        for (int ic = 0; ic < ICCHUNK; ++ic) {
#pragma unroll
            for (int dz = 0; dz < 3; ++dz) {
                const float* sl = &slab[ic][dz][yl * PSX + xc];
#pragma unroll
                for (int t9 = 0; t9 < 9; ++t9) {
                    const int dy = t9 / 3, dx = t9 % 3;
                    ull xd = dup2(sl[dy * PSX + dx]);
                    const ull* wp = (const ull*)&wsm[ic][dz * 9 + t9][0];
#pragma unroll
                    for (int o2 = 0; o2 < 8; ++o2) fma2(acc[o2], wp[o2], xd);
                }
            }
        }
    }

    // vectorized stores: thread owns 16 consecutive channels for its voxel
    const int i = z * 400 + yg * 20 + xc;
    if (g == 0) {
        float4* qd = (float4*)(g_Q + ((size_t)b * N_SPAT + i) * DQK);
        qd[0] = make_float4(lo32(acc[0]), hi32(acc[0]), lo32(acc[1]), hi32(acc[1]));
        qd[1] = make_float4(lo32(acc[2]), hi32(acc[2]), lo32(acc[3]), hi32(acc[3]));
        float4* kd = (float4*)(g_K + ((size_t)b * N_SPAT + i) * DQK);
        kd[0] = make_float4(lo32(acc[4]), hi32(acc[4]), lo32(acc[5]), hi32(acc[5]));
        kd[1] = make_float4(lo32(acc[6]), hi32(acc[6]), lo32(acc[7]), hi32(acc[7]));
    } else {
        float4* vd = (float4*)(g_V + ((size_t)b * N_SPAT + i) * DV + (g - 1) * 16);
#pragma unroll
        for (int q = 0; q < 4; ++q)
            vd[q] = make_float4(lo32(acc[2 * q]), hi32(acc[2 * q]),
                                lo32(acc[2 * q + 1]), hi32(acc[2 * q + 1]));
    }
}

// =====================================================================
// Flash attention kernel (split-KV partials) — R5 structure,
// phase A upgraded to FFMA2 with packed score pairs.
// BM=64 rows/CTA, 64 threads, 8x8 micro-tile, grid (125,2,JSPLIT).
// P exchanged by intra-warp shuffle (proven fastest).
// =====================================================================
#define BM 64
#define BN 64
#define ATT_T 64

__global__ __launch_bounds__(ATT_T, 4) void attn_kernel()
{
    __shared__ __align__(16) float sQT[DQK][BM];       // Q^T, pre-scaled log2(e)
    __shared__ __align__(16) float sKT[2][DQK][BN];    // K^T per buffer
    __shared__ __align__(16) float sV[2][BN][DV];      // V rows per buffer

    const int b = blockIdx.y;
    const int sp = blockIdx.z;
    const int i0 = blockIdx.x * BM;
    const int tid = threadIdx.x;
    const int tc = tid & 7;
    const int tr = tid >> 3;         // 0..7, rows 8tr..8tr+7
    const int lane = tid & 31;

    const int t0 = sp * (N_SPAT / BN / JSPLIT);       // 25 tiles per split
    const int t1 = t0 + (N_SPAT / BN / JSPLIT);

    const float* Qb = g_Q + (size_t)b * N_SPAT * DQK;
    const float* Kb = g_K + (size_t)b * N_SPAT * DQK;
    const float* Vb = g_V + (size_t)b * N_SPAT * DV;

    // ---- load Q tile (row per thread), transpose, pre-scale ----
    {
        const float4* qp = (const float4*)(Qb + (size_t)(i0 + tid) * DQK);
        float4 q0 = qp[0], q1 = qp[1];
        sQT[0][tid] = q0.x * LOG2E_F; sQT[1][tid] = q0.y * LOG2E_F;
        sQT[2][tid] = q0.z * LOG2E_F; sQT[3][tid] = q0.w * LOG2E_F;
        sQT[4][tid] = q1.x * LOG2E_F; sQT[5][tid] = q1.y * LOG2E_F;
        sQT[6][tid] = q1.z * LOG2E_F; sQT[7][tid] = q1.w * LOG2E_F;
    }

    float m[8], l[8];
    ull o[8][4];
#pragma unroll
    for (int ii = 0; ii < 8; ++ii) {
        m[ii] = -CUDART_INF_F;
        l[ii] = 0.f;
#pragma unroll
        for (int c2 = 0; c2 < 4; ++c2) o[ii][c2] = 0ull;
    }

    // ---- prologue: stage tile t0 into buffer 0 ----
    {
        const float* ksrc = Kb + (size_t)t0 * BN * DQK;
        float4 k0 = ((const float4*)ksrc)[2 * tid];
        float4 k1 = ((const float4*)ksrc)[2 * tid + 1];
        const float* vsrc = Vb + (size_t)t0 * BN * DV;
#pragma unroll
        for (int q = 0; q < 16; ++q)
            cp_async16(&((float*)sV[0])[(tid + q * 64) * 4], vsrc + (size_t)(tid + q * 64) * 4);
        cp_commit();
        sKT[0][0][tid] = k0.x; sKT[0][1][tid] = k0.y;
        sKT[0][2][tid] = k0.z; sKT[0][3][tid] = k0.w;
        sKT[0][4][tid] = k1.x; sKT[0][5][tid] = k1.y;
        sKT[0][6][tid] = k1.z; sKT[0][7][tid] = k1.w;
        cp_wait0();
        __syncthreads();
    }

    for (int it = t0; it < t1; ++it) {
        const int cur = (it - t0) & 1;
        const int nxt = cur ^ 1;
        const bool pref = (it + 1 < t1);
        float4 k0r, k1r;
        if (pref) {
            const float* ksrc = Kb + (size_t)(it + 1) * BN * DQK;
            k0r = ((const float4*)ksrc)[2 * tid];
            k1r = ((const float4*)ksrc)[2 * tid + 1];
            const float* vsrc = Vb + (size_t)(it + 1) * BN * DV;
#pragma unroll
            for (int q = 0; q < 16; ++q)
                cp_async16(&((float*)sV[nxt])[(tid + q * 64) * 4], vsrc + (size_t)(tid + q * 64) * 4);
            cp_commit();
        }

        // ---- phase A: S = Q K^T (8x8 micro-tile, k=8, FFMA2 pairs) ----
        // s2[ii][jp] = packed (S[ii][2jp], S[ii][2jp+1])
        ull s2[8][4];
#pragma unroll
        for (int ii = 0; ii < 8; ++ii)
#pragma unroll
            for (int jp = 0; jp < 4; ++jp) s2[ii][jp] = 0ull;

#pragma unroll
        for (int k = 0; k < DQK; ++k) {
            float4 qa = *(const float4*)&sQT[k][8 * tr];
            float4 qb = *(const float4*)&sQT[k][8 * tr + 4];
            const ulonglong2* kp = (const ulonglong2*)&sKT[cur][k][8 * tc];
            ulonglong2 k01 = kp[0];          // pairs (j0,j1),(j2,j3)
            ulonglong2 k23 = kp[1];          // pairs (j4,j5),(j6,j7)
            float qv[8] = {qa.x, qa.y, qa.z, qa.w, qb.x, qb.y, qb.z, qb.w};
#pragma unroll
            for (int ii = 0; ii < 8; ++ii) {
                ull qd = dup2(qv[ii]);
                fma2(s2[ii][0], k01.x, qd);
                fma2(s2[ii][1], k01.y, qd);
                fma2(s2[ii][2], k23.x, qd);
                fma2(s2[ii][3], k23.y, qd);
            }
        }

        // ---- online softmax (base-2 domain, halves read free) ----
#pragma unroll
        for (int ii = 0; ii < 8; ++ii) {
            float mx = lo32(s2[ii][0]);
            mx = fmaxf(mx, hi32(s2[ii][0]));
#pragma unroll
            for (int jp = 1; jp < 4; ++jp) {
                mx = fmaxf(mx, lo32(s2[ii][jp]));
                mx = fmaxf(mx, hi32(s2[ii][jp]));
            }
            mx = fmaxf(mx, __shfl_xor_sync(0xffffffffu, mx, 1));
            mx = fmaxf(mx, __shfl_xor_sync(0xffffffffu, mx, 2));
            mx = fmaxf(mx, __shfl_xor_sync(0xffffffffu, mx, 4));
            float mnew = fmaxf(m[ii], mx);
            float alpha = exp2f(m[ii] - mnew);
            m[ii] = mnew;
            float rs = 0.f;
#pragma unroll
            for (int jp = 0; jp < 4; ++jp) {
                float plo = exp2f(lo32(s2[ii][jp]) - mnew);
                float phi = exp2f(hi32(s2[ii][jp]) - mnew);
                s2[ii][jp] = pack2(plo, phi);   // now holds P pair
                rs += plo + phi;
            }
            rs += __shfl_xor_sync(0xffffffffu, rs, 1);
            rs += __shfl_xor_sync(0xffffffffu, rs, 2);
            rs += __shfl_xor_sync(0xffffffffu, rs, 4);
            l[ii] = l[ii] * alpha + rs;
            ull a2 = dup2(alpha);
#pragma unroll
            for (int c2 = 0; c2 < 4; ++c2) o[ii][c2] = mul2(o[ii][c2], a2);
        }

        // ---- phase C: O += P @ V  (P broadcast via shuffle, FFMA2) ----
#pragma unroll
        for (int ko = 0; ko < 8; ++ko) {
#pragma unroll
            for (int jj = 0; jj < 8; ++jj) {
                int k = ko * 8 + jj;
                const ulonglong2* vp = (const ulonglong2*)&sV[cur][k][8 * tc];
                ulonglong2 v01 = vp[0];
                ulonglong2 v23 = vp[1];
                int srcLane = (lane & 24) | ko;
#pragma unroll
                for (int ii = 0; ii < 8; ++ii) {
                    float pl = (jj & 1) ? hi32(s2[ii][jj >> 1]) : lo32(s2[ii][jj >> 1]);
                    float pv = __shfl_sync(0xffffffffu, pl, srcLane);
                    ull pd = dup2(pv);
                    fma2(o[ii][0], v01.x, pd);
                    fma2(o[ii][1], v01.y, pd);
                    fma2(o[ii][2], v23.x, pd);
                    fma2(o[ii][3], v23.y, pd);
                }
            }
        }

        if (pref) {
            sKT[nxt][0][tid] = k0r.x; sKT[nxt][1][tid] = k0r.y;
            sKT[nxt][2][tid] = k0r.z; sKT[nxt][3][tid] = k0r.w;
            sKT[nxt][4][tid] = k1r.x; sKT[nxt][5][tid] = k1r.y;
            sKT[nxt][6][tid] = k1r.z; sKT[nxt][7][tid] = k1r.w;
        }
        cp_wait0();
        __syncthreads();
    }

    // ---- epilogue: write unnormalized partials + (m,l) ----
    const size_t sb = (size_t)(sp * 2 + b);
#pragma unroll
    for (int ii = 0; ii < 8; ++ii) {
        int i = i0 + 8 * tr + ii;
        float* dst = g_Opart + (sb * N_SPAT + i) * DV + 8 * tc;
        ((float4*)dst)[0] = make_float4(lo32(o[ii][0]), hi32(o[ii][0]),
                                        lo32(o[ii][1]), hi32(o[ii][1]));
        ((float4*)dst)[1] = make_float4(lo32(o[ii][2]), hi32(o[ii][2]),
                                        lo32(o[ii][3]), hi32(o[ii][3]));
        if (tc == 0) {
            g_m[sb * N_SPAT + i] = m[ii];
            g_l[sb * N_SPAT + i] = l[ii];
        }
    }
}

// =====================================================================
// Merge kernel: combine JSPLIT partials (log-sum-exp, base-2 domain),
// transpose via smem, coalesced out[b][c][i] writes.
// =====================================================================
__global__ __launch_bounds__(256) void merge_kernel(float* __restrict__ out)
{
    __shared__ float T[DV][65];   // [c][i_local]

    const int b = blockIdx.y;
    const int i0 = blockIdx.x * 64;
    const int tid = threadIdx.x;
    const int il = tid >> 2;          // 0..63
    const int cq = tid & 3;           // channel quad group
    const int i = i0 + il;

    float mm[JSPLIT], coef[JSPLIT];
    float mstar = -CUDART_INF_F;
#pragma unroll
    for (int s = 0; s < JSPLIT; ++s) {
        mm[s] = g_m[((size_t)(s * 2 + b)) * N_SPAT + i];
        mstar = fmaxf(mstar, mm[s]);
    }
    float denom = 0.f;
#pragma unroll
    for (int s = 0; s < JSPLIT; ++s) {
        coef[s] = exp2f(mm[s] - mstar);
        denom += coef[s] * g_l[((size_t)(s * 2 + b)) * N_SPAT + i];
    }
    const float inv = 1.0f / denom;

    float acc[16];
#pragma unroll
    for (int e = 0; e < 16; ++e) acc[e] = 0.f;
#pragma unroll
    for (int s = 0; s < JSPLIT; ++s) {
        const float4* src = (const float4*)(g_Opart +
            (((size_t)(s * 2 + b)) * N_SPAT + i) * DV + cq * 16);
        float c = coef[s];
#pragma unroll
        for (int q = 0; q < 4; ++q) {
            float4 f = src[q];
            acc[4 * q + 0] = fmaf(c, f.x, acc[4 * q + 0]);
            acc[4 * q + 1] = fmaf(c, f.y, acc[4 * q + 1]);
            acc[4 * q + 2] = fmaf(c, f.z, acc[4 * q + 2]);
            acc[4 * q + 3] = fmaf(c, f.w, acc[4 * q + 3]);
        }
    }
#pragma unroll
    for (int e = 0; e < 16; ++e) T[cq * 16 + e][il] = acc[e] * inv;
    __syncthreads();

    {
        const int c = tid >> 2;
        const int ich = (tid & 3) * 16;
        float* dst = out + ((size_t)b * DV + c) * N_SPAT + i0 + ich;
#pragma unroll
        for (int q = 0; q < 4; ++q)
            ((float4*)dst)[q] = make_float4(T[c][ich + 4 * q + 0], T[c][ich + 4 * q + 1],
                                            T[c][ich + 4 * q + 2], T[c][ich + 4 * q + 3]);
    }
}

// =====================================================================
extern "C" void kernel_launch(void* const* d_in, const int* in_sizes, int n_in,
                              void* d_out, int out_size)
{
    const float* x  = (const float*)d_in[0];
    const float* wq = (const float*)d_in[1];
    const float* bq = (const float*)d_in[2];
    const float* wk = (const float*)d_in[3];
    const float* bk = (const float*)d_in[4];
    const float* wv = (const float*)d_in[5];
    const float* bv = (const float*)d_in[6];
    float* out = (float*)d_out;

    dim3 cgrid(5, 40, 2);                 // ocGroup, z*2+yhalf, batch
    conv_qkv_kernel<<<cgrid, CONV_T>>>(x, wq, bq, wk, bk, wv, bv);

    dim3 agrid(N_SPAT / BM, 2, JSPLIT);   // 125 x 2 x 5 = 1250 CTAs
    attn_kernel<<<agrid, ATT_T>>>();

    dim3 mgrid(N_SPAT / 64, 2);
    merge_kernel<<<mgrid, 256>>>(out);
}